// round 12
// baseline (speedup 1.0000x reference)
#include <cuda_runtime.h>
#include <cuda_bf16.h>
#include <cstdint>

#define Bsz  2
#define Tlen 512
#define Dm   256
#define Mrows (Bsz*Tlen)
#define NCH  (Bsz*Dm)        // 512 channels

#define NC 32                // chunks per channel
#define LC (Tlen/NC)         // 16 steps per chunk

// Scratch (allocation-free rule: __device__ globals)
__device__ float g_k  [Mrows*Dm];
__device__ float g_v  [Mrows*Dm];
__device__ float g_r  [Mrows*Dm];
__device__ float g_wkv[Mrows*Dm];

// ===========================================================================
// helpers
// ===========================================================================
__device__ __forceinline__ uint32_t pack_bf16(float a, float b) {
    __nv_bfloat162 h = __floats2bfloat162_rn(a, b);
    return *reinterpret_cast<uint32_t*>(&h);
}

__device__ __forceinline__ void mma_bf16(float c[4],
                                         uint32_t a0, uint32_t a1, uint32_t a2, uint32_t a3,
                                         uint32_t b0, uint32_t b1) {
    asm volatile(
        "mma.sync.aligned.m16n8k16.row.col.f32.bf16.bf16.f32 "
        "{%0,%1,%2,%3}, {%4,%5,%6,%7}, {%8,%9}, {%0,%1,%2,%3};"
        : "+f"(c[0]), "+f"(c[1]), "+f"(c[2]), "+f"(c[3])
        : "r"(a0), "r"(a1), "r"(a2), "r"(a3), "r"(b0), "r"(b1));
}

// ===========================================================================
// GEMM via mma.sync bf16x3-split, double-buffered smem pipeline.
// C[m,n] = sum_k A[m,k] * W[n,k], fp32 acc.
// Tile 64x64x32, 128 threads, 2x2 warp grid, warp tile 32x32.
// MODE 0: A = time-mixed x (kvr);  MODE 1: A = wkv * sigmoid(r) (out).
//
// Smem k-layout is permuted so each thread's two k16-half fragments are
// adjacent u32s -> LDS.64. Storage col kp_new = s*8 + t*2 + h for original
// kp_orig = s*8 + h*4 + t. Pitch 20 u32: 20g mod 32 covers all multiples of 4
// -> conflict-free LDS.64 across the 8 g-groups; 80B rows keep 8B alignment.
// ===========================================================================
#define BK 32
#define PITCH 20

template<int MODE>
__global__ void __launch_bounds__(128) mma_gemm(
    const float* __restrict__ x, const float* __restrict__ last_x,
    const float* __restrict__ mk, const float* __restrict__ mv,
    const float* __restrict__ mr,
    const float* __restrict__ Wk, const float* __restrict__ Wv,
    const float* __restrict__ Wr,
    float* __restrict__ out_override)
{
    __shared__ uint32_t Ah[2][64][PITCH], Al[2][64][PITCH];
    __shared__ uint32_t Bh[2][64][PITCH], Bl[2][64][PITCH];

    const int tid  = threadIdx.x;
    const int wid  = tid >> 5;
    const int lane = tid & 31;
    const int g    = lane >> 2;     // 0..7
    const int t    = lane & 3;      // 0..3
    const int wm   = wid & 1;       // warp m index
    const int wn   = wid >> 1;      // warp n index
    const int m0   = blockIdx.x * 64;
    const int n0   = blockIdx.y * 64;
    const int z    = blockIdx.z;

    const float* mixp = (z==0) ? mk  : (z==1) ? mv  : mr;
    const float* Wp   = (MODE==1) ? Wk /*Wo passed via Wk slot*/ :
                        ((z==0) ? Wk : (z==1) ? Wv : Wr);
    float* outp = (MODE==1) ? out_override :
                  ((z==0) ? g_k : (z==1) ? g_v : g_r);

    // staging thread -> (row, kp_orig): coalesced LDG (16 lanes x 8B = 128B)
    const int st_row = tid >> 4;          // 0..7 (+8e)
    const int st_kpo = tid & 15;          // original k-pair 0..15
    const int st_q   = st_kpo & 7;
    const int st_kpn = (st_kpo & 8) + ((st_q & 3) << 1) + (st_q >> 2); // storage col

    float2 a_val[8], b_val[8];

    // ---- stage-load k-tile: raw fp32 values into registers ----
    auto stage_load = [&](int k0) {
        const int gk = k0 + st_kpo*2;
        #pragma unroll
        for (int e = 0; e < 8; e++) {
            int m = m0 + st_row + e*8;
            if (MODE == 0) {
                int tt = m & (Tlen-1);
                float2 xc = *(const float2*)&x[(size_t)m*Dm + gk];
                float2 xp = (tt==0) ? *(const float2*)&last_x[(m>>9)*Dm + gk]
                                    : *(const float2*)&x[(size_t)(m-1)*Dm + gk];
                float2 mx = *(const float2*)&mixp[gk];
                a_val[e].x = fmaf(xc.x - xp.x, mx.x, xp.x);
                a_val[e].y = fmaf(xc.y - xp.y, mx.y, xp.y);
            } else {
                float2 wv = *(const float2*)&g_wkv[(size_t)m*Dm + gk];
                float2 rr = *(const float2*)&g_r  [(size_t)m*Dm + gk];
                a_val[e].x = wv.x * __fdividef(1.f, 1.f + __expf(-rr.x));
                a_val[e].y = wv.y * __fdividef(1.f, 1.f + __expf(-rr.y));
            }
            int n = n0 + st_row + e*8;
            b_val[e] = *(const float2*)&Wp[(size_t)n*Dm + gk];
        }
    };

    // ---- convert + STS into buffer bb ----
    auto stage_sts = [&](int bb) {
        #pragma unroll
        for (int e = 0; e < 8; e++) {
            int row = st_row + e*8;
            float h0 = __bfloat162float(__float2bfloat16(a_val[e].x));
            float h1 = __bfloat162float(__float2bfloat16(a_val[e].y));
            Ah[bb][row][st_kpn] = pack_bf16(h0, h1);
            Al[bb][row][st_kpn] = pack_bf16(a_val[e].x - h0, a_val[e].y - h1);
            float w0 = __bfloat162float(__float2bfloat16(b_val[e].x));
            float w1 = __bfloat162float(__float2bfloat16(b_val[e].y));
            Bh[bb][row][st_kpn] = pack_bf16(w0, w1);
            Bl[bb][row][st_kpn] = pack_bf16(b_val[e].x - w0, b_val[e].y - w1);
        }
    };

    float acc[2][4][4];
    #pragma unroll
    for (int mi=0;mi<2;mi++)
        #pragma unroll
        for (int ni=0;ni<4;ni++)
            #pragma unroll
            for (int q=0;q<4;q++) acc[mi][ni][q]=0.f;

    stage_load(0);
    stage_sts(0);
    __syncthreads();

    const int NKT = Dm / BK;   // 8
    for (int kt = 0; kt < NKT; kt++) {
        const int bb = kt & 1;
        if (kt + 1 < NKT) stage_load((kt+1) * BK);   // prefetch during compute

        #pragma unroll
        for (int s = 0; s < 2; s++) {
            const int col = s*8 + 2*t;
            uint32_t ah[2][4], al[2][4], bh[4][2], bl[4][2];
            #pragma unroll
            for (int mi = 0; mi < 2; mi++) {
                int r = wm*32 + mi*16 + g;
                uint2 q0 = *(const uint2*)&Ah[bb][r  ][col];
                uint2 q1 = *(const uint2*)&Ah[bb][r+8][col];
                ah[mi][0]=q0.x; ah[mi][2]=q0.y; ah[mi][1]=q1.x; ah[mi][3]=q1.y;
                uint2 p0 = *(const uint2*)&Al[bb][r  ][col];
                uint2 p1 = *(const uint2*)&Al[bb][r+8][col];
                al[mi][0]=p0.x; al[mi][2]=p0.y; al[mi][1]=p1.x; al[mi][3]=p1.y;
            }
            #pragma unroll
            for (int ni = 0; ni < 4; ni++) {
                int n = wn*32 + ni*8 + g;
                uint2 qb = *(const uint2*)&Bh[bb][n][col];
                bh[ni][0]=qb.x; bh[ni][1]=qb.y;
                uint2 pb = *(const uint2*)&Bl[bb][n][col];
                bl[ni][0]=pb.x; bl[ni][1]=pb.y;
            }
            #pragma unroll
            for (int mi = 0; mi < 2; mi++)
                #pragma unroll
                for (int ni = 0; ni < 4; ni++) {
                    mma_bf16(acc[mi][ni], ah[mi][0],ah[mi][1],ah[mi][2],ah[mi][3],
                             bh[ni][0], bh[ni][1]);
                    mma_bf16(acc[mi][ni], ah[mi][0],ah[mi][1],ah[mi][2],ah[mi][3],
                             bl[ni][0], bl[ni][1]);
                    mma_bf16(acc[mi][ni], al[mi][0],al[mi][1],al[mi][2],al[mi][3],
                             bh[ni][0], bh[ni][1]);
                }
        }

        if (kt + 1 < NKT) {
            stage_sts((kt+1) & 1);   // write other buffer; readers of it synced last iter
            __syncthreads();
        }
    }

    // ---- epilogue: C[g(+8)][2t,2t+1] per fragment ----
    #pragma unroll
    for (int mi = 0; mi < 2; mi++) {
        #pragma unroll
        for (int ni = 0; ni < 4; ni++) {
            int m = m0 + wm*32 + mi*16 + g;
            int n = n0 + wn*32 + ni*8 + 2*t;
            *(float2*)&outp[(size_t)m*Dm + n] =
                make_float2(acc[mi][ni][0], acc[mi][ni][1]);
            *(float2*)&outp[(size_t)(m+8)*Dm + n] =
                make_float2(acc[mi][ni][2], acc[mi][ni][3]);
        }
    }
}

// ===========================================================================
// Fused WKV scan.  One block per 32 channels; threadIdx.y = chunk.
// p1 reduction -> smem -> in-block prefix combine -> p2 replay.
// ===========================================================================
#define PF 8
__global__ void __launch_bounds__(1024) wkv_fused(
    const float* __restrict__ x,
    const float* __restrict__ last_num,
    const float* __restrict__ last_den,
    const float* __restrict__ td,
    const float* __restrict__ tf,
    float* __restrict__ states)
{
    __shared__ float s_num[NC][33];
    __shared__ float s_den[NC][33];

    const int lane = threadIdx.x;        // channel in group (0..31)
    const int c    = threadIdx.y;        // chunk (0..31)
    const int ch   = blockIdx.x * 32 + lane;
    const int b    = ch >> 8;
    const int d    = ch & (Dm-1);

    const float ew = __expf(-__expf(td[d]));
    const size_t base = (size_t)b*Tlen*Dm + (size_t)c*LC*Dm + d;
    const float* kp = g_k + base;
    const float* vp = g_v + base;

    // ---- pass 1: chunk-local affine reduction over LC=16 ----
    float ka[PF], va[PF], kb[PF], vb[PF];
    #pragma unroll
    for (int i=0;i<PF;i++){ ka[i]=kp[i*Dm];        va[i]=vp[i*Dm]; }
    #pragma unroll
    for (int i=0;i<PF;i++){ kb[i]=kp[(PF+i)*Dm];   vb[i]=vp[(PF+i)*Dm]; }

    float num = 0.f, den = 0.f;
    float ea[PF], eb[PF];
    #pragma unroll
    for (int i=0;i<PF;i++) ea[i] = __expf(ka[i]);
    #pragma unroll
    for (int i=0;i<PF;i++) eb[i] = __expf(kb[i]);
    #pragma unroll
    for (int i=0;i<PF;i++){ num = fmaf(ew, num, ea[i]*va[i]); den = fmaf(ew, den, ea[i]); }
    #pragma unroll
    for (int i=0;i<PF;i++){ num = fmaf(ew, num, eb[i]*vb[i]); den = fmaf(ew, den, eb[i]); }

    s_num[c][lane] = num;
    s_den[c][lane] = den;
    __syncthreads();

    // ---- combine: first chunk-row does 32-step prefix per channel ----
    if (c == 0) {
        float e2 = ew*ew, e4 = e2*e2, e8 = e4*e4;
        float ewL = e8*e8;                 // ew^16
        float rn = last_num[ch];
        float rd = last_den[ch];
        #pragma unroll
        for (int cc = 0; cc < NC; cc++) {
            float tn  = s_num[cc][lane];
            float tdn = s_den[cc][lane];
            s_num[cc][lane] = rn;
            s_den[cc][lane] = rd;
            rn = fmaf(ewL, rn, tn);
            rd = fmaf(ewL, rd, tdn);
        }
        states[ch]         = x[((size_t)b*Tlen + Tlen-1)*Dm + d];
        states[NCH + ch]   = rn;
        states[2*NCH + ch] = rd;
    }
    __syncthreads();

    // ---- pass 2: replay from chunk start state ----
    num = s_num[c][lane];
    den = s_den[c][lane];
    const float eu = __expf(tf[d]);
    float* wp = g_wkv + base;

    #pragma unroll
    for (int i=0;i<PF;i++){
        float ekv = ea[i]*va[i];
        wp[i*Dm] = __fdividef(fmaf(eu, ekv, num), fmaf(eu, ea[i], den));
        num = fmaf(ew, num, ekv);
        den = fmaf(ew, den, ea[i]);
    }
    #pragma unroll
    for (int i=0;i<PF;i++){
        float ekv = eb[i]*vb[i];
        wp[(PF+i)*Dm] = __fdividef(fmaf(eu, ekv, num), fmaf(eu, eb[i], den));
        num = fmaf(ew, num, ekv);
        den = fmaf(ew, den, eb[i]);
    }
}

// ---------------------------------------------------------------------------
extern "C" void kernel_launch(void* const* d_in, const int* in_sizes, int n_in,
                              void* d_out, int out_size)
{
    const float* x        = (const float*)d_in[0];
    const float* last_x   = (const float*)d_in[1];
    const float* last_num = (const float*)d_in[2];
    const float* last_den = (const float*)d_in[3];
    const float* td       = (const float*)d_in[4];
    const float* tf       = (const float*)d_in[5];
    const float* mk       = (const float*)d_in[6];
    const float* mv       = (const float*)d_in[7];
    const float* mr       = (const float*)d_in[8];
    const float* Wk       = (const float*)d_in[9];
    const float* Wv       = (const float*)d_in[10];
    const float* Wr       = (const float*)d_in[11];
    const float* Wo       = (const float*)d_in[12];
    float* out = (float*)d_out;

    // kvr: 3 fused time-mix GEMMs
    mma_gemm<0><<<dim3(Mrows/64, Dm/64, 3), 128>>>(
        x, last_x, mk, mv, mr, Wk, Wv, Wr, nullptr);
    // fused scan (also writes the 3 state outputs)
    wkv_fused<<<NCH/32, dim3(32,32)>>>(
        x, last_num, last_den, td, tf, out + (size_t)Mrows*Dm);
    // out = (wkv * sigmoid(r)) @ Wo^T   (Wo passed via the Wk slot)
    mma_gemm<1><<<dim3(Mrows/64, Dm/64, 1), 128>>>(
        x, last_x, mk, mv, mr, Wo, Wv, Wr, out);
}

// round 13
// speedup vs baseline: 1.3368x; 1.3368x over previous
#include <cuda_runtime.h>
#include <cuda_bf16.h>
#include <cstdint>

#define Bsz  2
#define Tlen 512
#define Dm   256
#define Mrows (Bsz*Tlen)
#define NCH  (Bsz*Dm)        // 512 channels
#define KP   (Dm/2)          // 128 packed u32 per row

#define NC 32                // chunks per channel
#define LC (Tlen/NC)         // 16 steps per chunk

// Scratch (allocation-free rule: __device__ globals)
__device__ float    g_k  [Mrows*Dm];
__device__ float    g_v  [Mrows*Dm];
__device__ float    g_r  [Mrows*Dm];
__device__ uint32_t g_Ah [3*Mrows*KP];   // prepacked bf16-hi of mixed A (3 variants)
__device__ uint32_t g_Al [3*Mrows*KP];   // bf16-lo residual
__device__ uint32_t g_Wh [4*Dm*KP];      // Wk,Wv,Wr,Wo hi
__device__ uint32_t g_Wl [4*Dm*KP];      // lo
__device__ uint32_t g_A2h[Mrows*KP];     // wkv*sigmoid(r) hi (out-GEMM A)
__device__ uint32_t g_A2l[Mrows*KP];     // lo

// ===========================================================================
// helpers
// ===========================================================================
__device__ __forceinline__ uint32_t pack_bf16(float a, float b) {
    __nv_bfloat162 h = __floats2bfloat162_rn(a, b);
    return *reinterpret_cast<uint32_t*>(&h);
}

__device__ __forceinline__ void mma_bf16(float c[4],
                                         uint32_t a0, uint32_t a1, uint32_t a2, uint32_t a3,
                                         uint32_t b0, uint32_t b1) {
    asm volatile(
        "mma.sync.aligned.m16n8k16.row.col.f32.bf16.bf16.f32 "
        "{%0,%1,%2,%3}, {%4,%5,%6,%7}, {%8,%9}, {%0,%1,%2,%3};"
        : "+f"(c[0]), "+f"(c[1]), "+f"(c[2]), "+f"(c[3])
        : "r"(a0), "r"(a1), "r"(a2), "r"(a3), "r"(b0), "r"(b1));
}

// ===========================================================================
// Prep: pack bf16 hi/lo for W (4 matrices) and mixed A (3 variants).
// Pair-slot id space: [0, 4*Dm*KP) = W;  [4*Dm*KP, +3*Mrows*KP) = A.
// ===========================================================================
#define WPREP (4*Dm*KP)          // 131072
#define APREP (3*Mrows*KP)       // 393216

__global__ void __launch_bounds__(256) prep(
    const float* __restrict__ x, const float* __restrict__ last_x,
    const float* __restrict__ mk, const float* __restrict__ mv,
    const float* __restrict__ mr,
    const float* __restrict__ Wk, const float* __restrict__ Wv,
    const float* __restrict__ Wr, const float* __restrict__ Wo)
{
    int i = blockIdx.x * 256 + threadIdx.x;
    if (i < WPREP) {
        int w   = i >> 15;               // Dm*KP = 32768 per matrix
        int rem = i & 32767;
        const float* W = (w==0) ? Wk : (w==1) ? Wv : (w==2) ? Wr : Wo;
        float2 v = *(const float2*)&W[rem*2];
        float h0 = __bfloat162float(__float2bfloat16(v.x));
        float h1 = __bfloat162float(__float2bfloat16(v.y));
        g_Wh[i] = pack_bf16(h0, h1);
        g_Wl[i] = pack_bf16(v.x - h0, v.y - h1);
    } else {
        int j   = i - WPREP;
        int z   = j >> 17;               // Mrows*KP = 131072 per variant
        int rem = j & 131071;
        int m   = rem >> 7;
        int kp  = rem & (KP-1);
        const float* mixp = (z==0) ? mk : (z==1) ? mv : mr;
        int gk = kp*2;
        int tt = m & (Tlen-1);
        float2 xc = *(const float2*)&x[(size_t)m*Dm + gk];
        float2 xp = (tt==0) ? *(const float2*)&last_x[(m>>9)*Dm + gk]
                            : *(const float2*)&x[(size_t)(m-1)*Dm + gk];
        float2 mx = *(const float2*)&mixp[gk];
        float a0 = fmaf(xc.x - xp.x, mx.x, xp.x);
        float a1 = fmaf(xc.y - xp.y, mx.y, xp.y);
        float h0 = __bfloat162float(__float2bfloat16(a0));
        float h1 = __bfloat162float(__float2bfloat16(a1));
        g_Ah[j] = pack_bf16(h0, h1);
        g_Al[j] = pack_bf16(a0 - h0, a1 - h1);
    }
}

// ===========================================================================
// GEMM via mma.sync bf16x3-split on prepacked operands.
// Tile 64x64x32, 256 threads, warp grid 2(m)x4(n), warp tile 32x16.
// MODE 0: A = g_Ah/g_Al variant z, W = g_Wh[z], out = g_k/v/r.
// MODE 1: A = g_A2h/g_A2l,         W = g_Wh[3] (Wo), out = final out.
// ===========================================================================
template<int MODE>
__global__ void __launch_bounds__(256) mma_gemm(float* __restrict__ out_final)
{
    __shared__ uint32_t Ah[64][17], Al[64][17], Bh[64][17], Bl[64][17];

    const int tid  = threadIdx.x;
    const int wid  = tid >> 5;
    const int lane = tid & 31;
    const int g    = lane >> 2;     // 0..7
    const int t    = lane & 3;      // 0..3
    const int wm   = wid & 1;       // warp m index (0..1)
    const int wn   = wid >> 1;      // warp n index (0..3)
    const int m0   = blockIdx.x * 64;
    const int n0   = blockIdx.y * 64;
    const int z    = (MODE==0) ? blockIdx.z : 3;

    const uint32_t* pAh = (MODE==0) ? g_Ah + (size_t)z*Mrows*KP : g_A2h;
    const uint32_t* pAl = (MODE==0) ? g_Al + (size_t)z*Mrows*KP : g_A2l;
    const uint32_t* pWh = g_Wh + (size_t)z*Dm*KP;
    const uint32_t* pWl = g_Wl + (size_t)z*Dm*KP;
    float* outp = (MODE==0) ? ((z==0) ? g_k : (z==1) ? g_v : g_r) : out_final;

    const int st_row0 = tid >> 4;    // 0..15 (+16 per e)
    const int st_kp   = tid & 15;

    float acc[2][2][4];
    #pragma unroll
    for (int mi=0;mi<2;mi++)
        #pragma unroll
        for (int ni=0;ni<2;ni++)
            #pragma unroll
            for (int q=0;q<4;q++) acc[mi][ni][q]=0.f;

    const int NKT = Dm/32;   // 8 k-tiles of 16 u32-pairs
    for (int kt = 0; kt < NKT; kt++) {
        const int kp0 = kt*16;
        // ---- stage prepacked tiles (no conversion) ----
        #pragma unroll
        for (int e = 0; e < 4; e++) {
            int row = st_row0 + e*16;
            size_t ai = (size_t)(m0+row)*KP + kp0 + st_kp;
            size_t bi = (size_t)(n0+row)*KP + kp0 + st_kp;
            Ah[row][st_kp] = pAh[ai];
            Al[row][st_kp] = pAl[ai];
            Bh[row][st_kp] = pWh[bi];
            Bl[row][st_kp] = pWl[bi];
        }
        __syncthreads();

        #pragma unroll
        for (int s = 0; s < 2; s++) {
            const int cb = s*8;
            uint32_t ah[2][4], al[2][4], bh[2][2], bl[2][2];
            #pragma unroll
            for (int mi = 0; mi < 2; mi++) {
                int r = wm*32 + mi*16 + g;
                ah[mi][0] = Ah[r  ][cb+t];   ah[mi][1] = Ah[r+8][cb+t];
                ah[mi][2] = Ah[r  ][cb+t+4]; ah[mi][3] = Ah[r+8][cb+t+4];
                al[mi][0] = Al[r  ][cb+t];   al[mi][1] = Al[r+8][cb+t];
                al[mi][2] = Al[r  ][cb+t+4]; al[mi][3] = Al[r+8][cb+t+4];
            }
            #pragma unroll
            for (int ni = 0; ni < 2; ni++) {
                int n = wn*16 + ni*8 + g;
                bh[ni][0] = Bh[n][cb+t]; bh[ni][1] = Bh[n][cb+t+4];
                bl[ni][0] = Bl[n][cb+t]; bl[ni][1] = Bl[n][cb+t+4];
            }
            #pragma unroll
            for (int mi = 0; mi < 2; mi++)
                #pragma unroll
                for (int ni = 0; ni < 2; ni++) {
                    mma_bf16(acc[mi][ni], ah[mi][0],ah[mi][1],ah[mi][2],ah[mi][3],
                             bh[ni][0], bh[ni][1]);
                    mma_bf16(acc[mi][ni], ah[mi][0],ah[mi][1],ah[mi][2],ah[mi][3],
                             bl[ni][0], bl[ni][1]);
                    mma_bf16(acc[mi][ni], al[mi][0],al[mi][1],al[mi][2],al[mi][3],
                             bh[ni][0], bh[ni][1]);
                }
        }
        __syncthreads();
    }

    // ---- epilogue ----
    #pragma unroll
    for (int mi = 0; mi < 2; mi++) {
        #pragma unroll
        for (int ni = 0; ni < 2; ni++) {
            int m = m0 + wm*32 + mi*16 + g;
            int n = n0 + wn*16 + ni*8 + 2*t;
            *(float2*)&outp[(size_t)m*Dm + n] =
                make_float2(acc[mi][ni][0], acc[mi][ni][1]);
            *(float2*)&outp[(size_t)(m+8)*Dm + n] =
                make_float2(acc[mi][ni][2], acc[mi][ni][3]);
        }
    }
}

// ===========================================================================
// Fused WKV scan.  One block per 32 channels; threadIdx.y = chunk.
// p1 reduction -> smem -> in-block prefix combine -> p2 replay.
// Pass 2 writes the out-GEMM A operand (wkv*sigmoid(r)) prepacked bf16 hi/lo.
// ===========================================================================
#define PF 8
__global__ void __launch_bounds__(1024) wkv_fused(
    const float* __restrict__ x,
    const float* __restrict__ last_num,
    const float* __restrict__ last_den,
    const float* __restrict__ td,
    const float* __restrict__ tf,
    float* __restrict__ states)
{
    __shared__ float s_num[NC][33];
    __shared__ float s_den[NC][33];

    const int lane = threadIdx.x;        // channel in group (0..31)
    const int c    = threadIdx.y;        // chunk (0..31)
    const int ch   = blockIdx.x * 32 + lane;
    const int b    = ch >> 8;
    const int d    = ch & (Dm-1);

    const float ew = __expf(-__expf(td[d]));
    const size_t base = (size_t)b*Tlen*Dm + (size_t)c*LC*Dm + d;
    const float* kp = g_k + base;
    const float* vp = g_v + base;
    const float* rp = g_r + base;

    // ---- pass 1: chunk-local affine reduction over LC=16 ----
    float ka[PF], va[PF], kb[PF], vb[PF];
    #pragma unroll
    for (int i=0;i<PF;i++){ ka[i]=kp[i*Dm];        va[i]=vp[i*Dm]; }
    #pragma unroll
    for (int i=0;i<PF;i++){ kb[i]=kp[(PF+i)*Dm];   vb[i]=vp[(PF+i)*Dm]; }

    float num = 0.f, den = 0.f;
    float ea[PF], eb[PF];
    #pragma unroll
    for (int i=0;i<PF;i++) ea[i] = __expf(ka[i]);
    #pragma unroll
    for (int i=0;i<PF;i++) eb[i] = __expf(kb[i]);
    #pragma unroll
    for (int i=0;i<PF;i++){ num = fmaf(ew, num, ea[i]*va[i]); den = fmaf(ew, den, ea[i]); }
    #pragma unroll
    for (int i=0;i<PF;i++){ num = fmaf(ew, num, eb[i]*vb[i]); den = fmaf(ew, den, eb[i]); }

    s_num[c][lane] = num;
    s_den[c][lane] = den;
    __syncthreads();

    // ---- combine: first chunk-row does 32-step prefix per channel ----
    if (c == 0) {
        float e2 = ew*ew, e4 = e2*e2, e8 = e4*e4;
        float ewL = e8*e8;                 // ew^16
        float rn = last_num[ch];
        float rd = last_den[ch];
        #pragma unroll
        for (int cc = 0; cc < NC; cc++) {
            float tn  = s_num[cc][lane];
            float tdn = s_den[cc][lane];
            s_num[cc][lane] = rn;
            s_den[cc][lane] = rd;
            rn = fmaf(ewL, rn, tn);
            rd = fmaf(ewL, rd, tdn);
        }
        states[ch]         = x[((size_t)b*Tlen + Tlen-1)*Dm + d];
        states[NCH + ch]   = rn;
        states[2*NCH + ch] = rd;
    }
    __syncthreads();

    // ---- pass 2: replay, emit packed A2 = wkv * sigmoid(r) ----
    num = s_num[c][lane];
    den = s_den[c][lane];
    const float eu = __expf(tf[d]);
    const int mrow0 = b*Tlen + c*LC;     // global row of step 0
    const int kpcol = d >> 1;
    const bool even = (lane & 1) == 0;

    float ra[PF], rb[PF];
    #pragma unroll
    for (int i=0;i<PF;i++) ra[i] = rp[i*Dm];
    #pragma unroll
    for (int i=0;i<PF;i++) rb[i] = rp[(PF+i)*Dm];

    #pragma unroll
    for (int i=0;i<PF;i++){
        float ekv = ea[i]*va[i];
        float wkv = __fdividef(fmaf(eu, ekv, num), fmaf(eu, ea[i], den));
        float a   = wkv * __fdividef(1.f, 1.f + __expf(-ra[i]));
        float an  = __shfl_down_sync(0xffffffffu, a, 1);
        if (even) {
            float h0 = __bfloat162float(__float2bfloat16(a));
            float h1 = __bfloat162float(__float2bfloat16(an));
            size_t o = (size_t)(mrow0 + i)*KP + kpcol;
            g_A2h[o] = pack_bf16(h0, h1);
            g_A2l[o] = pack_bf16(a - h0, an - h1);
        }
        num = fmaf(ew, num, ekv);
        den = fmaf(ew, den, ea[i]);
    }
    #pragma unroll
    for (int i=0;i<PF;i++){
        float ekv = eb[i]*vb[i];
        float wkv = __fdividef(fmaf(eu, ekv, num), fmaf(eu, eb[i], den));
        float a   = wkv * __fdividef(1.f, 1.f + __expf(-rb[i]));
        float an  = __shfl_down_sync(0xffffffffu, a, 1);
        if (even) {
            float h0 = __bfloat162float(__float2bfloat16(a));
            float h1 = __bfloat162float(__float2bfloat16(an));
            size_t o = (size_t)(mrow0 + PF + i)*KP + kpcol;
            g_A2h[o] = pack_bf16(h0, h1);
            g_A2l[o] = pack_bf16(a - h0, an - h1);
        }
        num = fmaf(ew, num, ekv);
        den = fmaf(ew, den, eb[i]);
    }
}

// ---------------------------------------------------------------------------
extern "C" void kernel_launch(void* const* d_in, const int* in_sizes, int n_in,
                              void* d_out, int out_size)
{
    const float* x        = (const float*)d_in[0];
    const float* last_x   = (const float*)d_in[1];
    const float* last_num = (const float*)d_in[2];
    const float* last_den = (const float*)d_in[3];
    const float* td       = (const float*)d_in[4];
    const float* tf       = (const float*)d_in[5];
    const float* mk       = (const float*)d_in[6];
    const float* mv       = (const float*)d_in[7];
    const float* mr       = (const float*)d_in[8];
    const float* Wk       = (const float*)d_in[9];
    const float* Wv       = (const float*)d_in[10];
    const float* Wr       = (const float*)d_in[11];
    const float* Wo       = (const float*)d_in[12];
    float* out = (float*)d_out;

    prep<<<(WPREP+APREP)/256, 256>>>(x, last_x, mk, mv, mr, Wk, Wv, Wr, Wo);
    mma_gemm<0><<<dim3(Mrows/64, Dm/64, 3), 256>>>(nullptr);
    wkv_fused<<<NCH/32, dim3(32,32)>>>(
        x, last_num, last_den, td, tf, out + (size_t)Mrows*Dm);
    mma_gemm<1><<<dim3(Mrows/64, Dm/64, 1), 256>>>(out);
}

// round 14
// speedup vs baseline: 1.7105x; 1.2796x over previous
#include <cuda_runtime.h>
#include <cuda_bf16.h>
#include <cstdint>

#define Bsz  2
#define Tlen 512
#define Dm   256
#define Mrows (Bsz*Tlen)
#define NCH  (Bsz*Dm)        // 512 channels
#define KP   (Dm/2)          // 128 packed u32 per row

#define NC 32                // chunks per channel
#define LC (Tlen/NC)         // 16 steps per chunk

// Scratch (allocation-free rule: __device__ globals)
__device__ float    g_k  [Mrows*Dm];
__device__ float    g_v  [Mrows*Dm];
__device__ float    g_r  [Mrows*Dm];
__device__ uint32_t g_Ah [3*Mrows*KP];   // prepacked bf16-hi of mixed A (3 variants)
__device__ uint32_t g_Al [3*Mrows*KP];   // bf16-lo residual
__device__ uint32_t g_Wh [4*Dm*KP];      // Wk,Wv,Wr,Wo hi
__device__ uint32_t g_Wl [4*Dm*KP];      // lo
__device__ uint32_t g_A2h[Mrows*KP];     // wkv*sigmoid(r) hi (out-GEMM A)
__device__ uint32_t g_A2l[Mrows*KP];     // lo

// ===========================================================================
// helpers
// ===========================================================================
__device__ __forceinline__ uint32_t pack_bf16(float a, float b) {
    __nv_bfloat162 h = __floats2bfloat162_rn(a, b);
    return *reinterpret_cast<uint32_t*>(&h);
}
__device__ __forceinline__ uint32_t smem_u32(const void* p) {
    uint32_t a;
    asm("{ .reg .u64 t; cvta.to.shared.u64 t, %1; cvt.u32.u64 %0, t; }"
        : "=r"(a) : "l"(p));
    return a;
}
__device__ __forceinline__ void mma_bf16(float c[4],
                                         uint32_t a0, uint32_t a1, uint32_t a2, uint32_t a3,
                                         uint32_t b0, uint32_t b1) {
    asm volatile(
        "mma.sync.aligned.m16n8k16.row.col.f32.bf16.bf16.f32 "
        "{%0,%1,%2,%3}, {%4,%5,%6,%7}, {%8,%9}, {%0,%1,%2,%3};"
        : "+f"(c[0]), "+f"(c[1]), "+f"(c[2]), "+f"(c[3])
        : "r"(a0), "r"(a1), "r"(a2), "r"(a3), "r"(b0), "r"(b1));
}
__device__ __forceinline__ void ldmx4(uint32_t& r0, uint32_t& r1,
                                      uint32_t& r2, uint32_t& r3, uint32_t addr) {
    asm volatile("ldmatrix.sync.aligned.m8n8.x4.shared.b16 {%0,%1,%2,%3}, [%4];"
                 : "=r"(r0), "=r"(r1), "=r"(r2), "=r"(r3) : "r"(addr));
}
__device__ __forceinline__ void cp16(uint32_t dst, const void* src) {
    asm volatile("cp.async.cg.shared.global [%0], [%1], 16;" :: "r"(dst), "l"(src));
}
#define CP_COMMIT() asm volatile("cp.async.commit_group;" ::: "memory")
#define CP_WAIT(N)  asm volatile("cp.async.wait_group %0;" :: "n"(N) : "memory")

// ===========================================================================
// Prep: pack bf16 hi/lo for W (4 matrices) and mixed A (3 variants).
// ===========================================================================
#define WPREP (4*Dm*KP)          // 131072
#define APREP (3*Mrows*KP)       // 393216

__global__ void __launch_bounds__(256) prep(
    const float* __restrict__ x, const float* __restrict__ last_x,
    const float* __restrict__ mk, const float* __restrict__ mv,
    const float* __restrict__ mr,
    const float* __restrict__ Wk, const float* __restrict__ Wv,
    const float* __restrict__ Wr, const float* __restrict__ Wo)
{
    int i = blockIdx.x * 256 + threadIdx.x;
    if (i < WPREP) {
        int w   = i >> 15;               // Dm*KP = 32768 per matrix
        int rem = i & 32767;
        const float* W = (w==0) ? Wk : (w==1) ? Wv : (w==2) ? Wr : Wo;
        float2 v = *(const float2*)&W[rem*2];
        float h0 = __bfloat162float(__float2bfloat16(v.x));
        float h1 = __bfloat162float(__float2bfloat16(v.y));
        g_Wh[i] = pack_bf16(h0, h1);
        g_Wl[i] = pack_bf16(v.x - h0, v.y - h1);
    } else {
        int j   = i - WPREP;
        int z   = j >> 17;               // Mrows*KP = 131072 per variant
        int rem = j & 131071;
        int m   = rem >> 7;
        int kp  = rem & (KP-1);
        const float* mixp = (z==0) ? mk : (z==1) ? mv : mr;
        int gk = kp*2;
        int tt = m & (Tlen-1);
        float2 xc = *(const float2*)&x[(size_t)m*Dm + gk];
        float2 xp = (tt==0) ? *(const float2*)&last_x[(m>>9)*Dm + gk]
                            : *(const float2*)&x[(size_t)(m-1)*Dm + gk];
        float2 mx = *(const float2*)&mixp[gk];
        float a0 = fmaf(xc.x - xp.x, mx.x, xp.x);
        float a1 = fmaf(xc.y - xp.y, mx.y, xp.y);
        float h0 = __bfloat162float(__float2bfloat16(a0));
        float h1 = __bfloat162float(__float2bfloat16(a1));
        g_Ah[j] = pack_bf16(h0, h1);
        g_Al[j] = pack_bf16(a0 - h0, a1 - h1);
    }
}

// ===========================================================================
// GEMM: mma.sync bf16x3-split, cp.async double-buffer, ldmatrix fragments.
// Tile 64x64x32, 128 threads, 2x2 warps, warp tile 32x32.
// Pitch 20 u32 (80B rows): 16B-aligned, conflict-free ldmatrix phases.
// ===========================================================================
#define PITCH 20

template<int MODE>
__global__ void __launch_bounds__(128) mma_gemm(float* __restrict__ out_final)
{
    __shared__ uint32_t SA[2][2][64][PITCH];   // [buf][hi/lo][row][kp]
    __shared__ uint32_t SB[2][2][64][PITCH];

    const int tid  = threadIdx.x;
    const int wid  = tid >> 5;
    const int lane = tid & 31;
    const int g    = lane >> 2;
    const int t    = lane & 3;
    const int wm   = wid & 1;
    const int wn   = wid >> 1;
    const int m0   = blockIdx.x * 64;
    const int n0   = blockIdx.y * 64;
    const int z    = (MODE==0) ? blockIdx.z : 3;

    const uint32_t* pAh = (MODE==0) ? g_Ah + (size_t)z*Mrows*KP : g_A2h;
    const uint32_t* pAl = (MODE==0) ? g_Al + (size_t)z*Mrows*KP : g_A2l;
    const uint32_t* pWh = g_Wh + (size_t)z*Dm*KP;
    const uint32_t* pWl = g_Wl + (size_t)z*Dm*KP;
    float* outp = (MODE==0) ? ((z==0) ? g_k : (z==1) ? g_v : g_r) : out_final;

    // staging: 1024 16B-chunks per k-tile (4 arrays x 64 rows x 4 colgrps) / 128 thr
    // chunk id c = tid + e*128: array = c>>8, row = (c&255)>>2, colgrp = (c&3)*4
    auto stage = [&](int kt, int bb) {
        const int kp0 = kt*16;
        #pragma unroll
        for (int e = 0; e < 8; e++) {
            int c   = tid + e*128;
            int arr = c >> 8;
            int row = (c & 255) >> 2;
            int cg  = (c & 3) * 4;
            const uint32_t* src;
            uint32_t dst;
            if (arr == 0)      { src = pAh + (size_t)(m0+row)*KP + kp0 + cg;
                                 dst = smem_u32(&SA[bb][0][row][cg]); }
            else if (arr == 1) { src = pAl + (size_t)(m0+row)*KP + kp0 + cg;
                                 dst = smem_u32(&SA[bb][1][row][cg]); }
            else if (arr == 2) { src = pWh + (size_t)(n0+row)*KP + kp0 + cg;
                                 dst = smem_u32(&SB[bb][0][row][cg]); }
            else               { src = pWl + (size_t)(n0+row)*KP + kp0 + cg;
                                 dst = smem_u32(&SB[bb][1][row][cg]); }
            cp16(dst, src);
        }
        CP_COMMIT();
    };

    float acc[2][4][4];
    #pragma unroll
    for (int mi=0;mi<2;mi++)
        #pragma unroll
        for (int ni=0;ni<4;ni++)
            #pragma unroll
            for (int q=0;q<4;q++) acc[mi][ni][q]=0.f;

    // ldmatrix lane addressing
    const int lrow = (lane & 7) + ((lane >> 3) & 1) * 8;  // row within 16-row group
    const int lcol = (lane >> 4) * 4;                      // 0 or 4

    stage(0, 0);

    const int NKT = Dm/32;   // 8
    for (int kt = 0; kt < NKT; kt++) {
        const int bb = kt & 1;
        if (kt + 1 < NKT) { stage(kt+1, bb^1); CP_WAIT(1); }
        else              { CP_WAIT(0); }
        __syncthreads();

        #pragma unroll
        for (int s = 0; s < 2; s++) {
            const int cb = s*8;
            uint32_t ah[2][4], al[2][4], bh[4][2], bl[4][2];
            #pragma unroll
            for (int mi = 0; mi < 2; mi++) {
                int r = wm*32 + mi*16 + lrow;
                ldmx4(ah[mi][0], ah[mi][1], ah[mi][2], ah[mi][3],
                      smem_u32(&SA[bb][0][r][cb + lcol]));
                ldmx4(al[mi][0], al[mi][1], al[mi][2], al[mi][3],
                      smem_u32(&SA[bb][1][r][cb + lcol]));
            }
            #pragma unroll
            for (int nh = 0; nh < 2; nh++) {
                int n = wn*32 + nh*16 + lrow;
                uint32_t q0,q1,q2,q3;
                ldmx4(q0, q1, q2, q3, smem_u32(&SB[bb][0][n][cb + lcol]));
                bh[nh*2][0]=q0; bh[nh*2+1][0]=q1; bh[nh*2][1]=q2; bh[nh*2+1][1]=q3;
                ldmx4(q0, q1, q2, q3, smem_u32(&SB[bb][1][n][cb + lcol]));
                bl[nh*2][0]=q0; bl[nh*2+1][0]=q1; bl[nh*2][1]=q2; bl[nh*2+1][1]=q3;
            }
            #pragma unroll
            for (int mi = 0; mi < 2; mi++)
                #pragma unroll
                for (int ni = 0; ni < 4; ni++) {
                    mma_bf16(acc[mi][ni], ah[mi][0],ah[mi][1],ah[mi][2],ah[mi][3],
                             bh[ni][0], bh[ni][1]);
                    mma_bf16(acc[mi][ni], ah[mi][0],ah[mi][1],ah[mi][2],ah[mi][3],
                             bl[ni][0], bl[ni][1]);
                    mma_bf16(acc[mi][ni], al[mi][0],al[mi][1],al[mi][2],al[mi][3],
                             bh[ni][0], bh[ni][1]);
                }
        }
        __syncthreads();   // all reads of buf bb done before kt+2 overwrites it
    }

    // ---- epilogue ----
    #pragma unroll
    for (int mi = 0; mi < 2; mi++) {
        #pragma unroll
        for (int ni = 0; ni < 4; ni++) {
            int m = m0 + wm*32 + mi*16 + g;
            int n = n0 + wn*32 + ni*8 + 2*t;
            *(float2*)&outp[(size_t)m*Dm + n] =
                make_float2(acc[mi][ni][0], acc[mi][ni][1]);
            *(float2*)&outp[(size_t)(m+8)*Dm + n] =
                make_float2(acc[mi][ni][2], acc[mi][ni][3]);
        }
    }
}

// ===========================================================================
// Fused WKV scan.  One block per 32 channels; threadIdx.y = chunk.
// Pass 2 writes the out-GEMM A operand (wkv*sigmoid(r)) prepacked bf16 hi/lo.
// ===========================================================================
#define PF 8
__global__ void __launch_bounds__(1024) wkv_fused(
    const float* __restrict__ x,
    const float* __restrict__ last_num,
    const float* __restrict__ last_den,
    const float* __restrict__ td,
    const float* __restrict__ tf,
    float* __restrict__ states)
{
    __shared__ float s_num[NC][33];
    __shared__ float s_den[NC][33];

    const int lane = threadIdx.x;
    const int c    = threadIdx.y;
    const int ch   = blockIdx.x * 32 + lane;
    const int b    = ch >> 8;
    const int d    = ch & (Dm-1);

    const float ew = __expf(-__expf(td[d]));
    const size_t base = (size_t)b*Tlen*Dm + (size_t)c*LC*Dm + d;
    const float* kp = g_k + base;
    const float* vp = g_v + base;
    const float* rp = g_r + base;

    float ka[PF], va[PF], kb[PF], vb[PF];
    #pragma unroll
    for (int i=0;i<PF;i++){ ka[i]=kp[i*Dm];        va[i]=vp[i*Dm]; }
    #pragma unroll
    for (int i=0;i<PF;i++){ kb[i]=kp[(PF+i)*Dm];   vb[i]=vp[(PF+i)*Dm]; }

    float num = 0.f, den = 0.f;
    float ea[PF], eb[PF];
    #pragma unroll
    for (int i=0;i<PF;i++) ea[i] = __expf(ka[i]);
    #pragma unroll
    for (int i=0;i<PF;i++) eb[i] = __expf(kb[i]);
    #pragma unroll
    for (int i=0;i<PF;i++){ num = fmaf(ew, num, ea[i]*va[i]); den = fmaf(ew, den, ea[i]); }
    #pragma unroll
    for (int i=0;i<PF;i++){ num = fmaf(ew, num, eb[i]*vb[i]); den = fmaf(ew, den, eb[i]); }

    s_num[c][lane] = num;
    s_den[c][lane] = den;
    __syncthreads();

    if (c == 0) {
        float e2 = ew*ew, e4 = e2*e2, e8 = e4*e4;
        float ewL = e8*e8;                 // ew^16
        float rn = last_num[ch];
        float rd = last_den[ch];
        #pragma unroll
        for (int cc = 0; cc < NC; cc++) {
            float tn  = s_num[cc][lane];
            float tdn = s_den[cc][lane];
            s_num[cc][lane] = rn;
            s_den[cc][lane] = rd;
            rn = fmaf(ewL, rn, tn);
            rd = fmaf(ewL, rd, tdn);
        }
        states[ch]         = x[((size_t)b*Tlen + Tlen-1)*Dm + d];
        states[NCH + ch]   = rn;
        states[2*NCH + ch] = rd;
    }
    __syncthreads();

    num = s_num[c][lane];
    den = s_den[c][lane];
    const float eu = __expf(tf[d]);
    const int mrow0 = b*Tlen + c*LC;
    const int kpcol = d >> 1;
    const bool even = (lane & 1) == 0;

    float ra[PF], rb[PF];
    #pragma unroll
    for (int i=0;i<PF;i++) ra[i] = rp[i*Dm];
    #pragma unroll
    for (int i=0;i<PF;i++) rb[i] = rp[(PF+i)*Dm];

    #pragma unroll
    for (int i=0;i<PF;i++){
        float ekv = ea[i]*va[i];
        float wkv = __fdividef(fmaf(eu, ekv, num), fmaf(eu, ea[i], den));
        float a   = wkv * __fdividef(1.f, 1.f + __expf(-ra[i]));
        float an  = __shfl_down_sync(0xffffffffu, a, 1);
        if (even) {
            float h0 = __bfloat162float(__float2bfloat16(a));
            float h1 = __bfloat162float(__float2bfloat16(an));
            size_t o = (size_t)(mrow0 + i)*KP + kpcol;
            g_A2h[o] = pack_bf16(h0, h1);
            g_A2l[o] = pack_bf16(a - h0, an - h1);
        }
        num = fmaf(ew, num, ekv);
        den = fmaf(ew, den, ea[i]);
    }
    #pragma unroll
    for (int i=0;i<PF;i++){
        float ekv = eb[i]*vb[i];
        float wkv = __fdividef(fmaf(eu, ekv, num), fmaf(eu, eb[i], den));
        float a   = wkv * __fdividef(1.f, 1.f + __expf(-rb[i]));
        float an  = __shfl_down_sync(0xffffffffu, a, 1);
        if (even) {
            float h0 = __bfloat162float(__float2bfloat16(a));
            float h1 = __bfloat162float(__float2bfloat16(an));
            size_t o = (size_t)(mrow0 + PF + i)*KP + kpcol;
            g_A2h[o] = pack_bf16(h0, h1);
            g_A2l[o] = pack_bf16(a - h0, an - h1);
        }
        num = fmaf(ew, num, ekv);
        den = fmaf(ew, den, eb[i]);
    }
}

// ---------------------------------------------------------------------------
extern "C" void kernel_launch(void* const* d_in, const int* in_sizes, int n_in,
                              void* d_out, int out_size)
{
    const float* x        = (const float*)d_in[0];
    const float* last_x   = (const float*)d_in[1];
    const float* last_num = (const float*)d_in[2];
    const float* last_den = (const float*)d_in[3];
    const float* td       = (const float*)d_in[4];
    const float* tf       = (const float*)d_in[5];
    const float* mk       = (const float*)d_in[6];
    const float* mv       = (const float*)d_in[7];
    const float* mr       = (const float*)d_in[8];
    const float* Wk       = (const float*)d_in[9];
    const float* Wv       = (const float*)d_in[10];
    const float* Wr       = (const float*)d_in[11];
    const float* Wo       = (const float*)d_in[12];
    float* out = (float*)d_out;

    prep<<<(WPREP+APREP)/256, 256>>>(x, last_x, mk, mv, mr, Wk, Wv, Wr, Wo);
    mma_gemm<0><<<dim3(Mrows/64, Dm/64, 3), 128>>>(nullptr);
    wkv_fused<<<NCH/32, dim3(32,32)>>>(
        x, last_num, last_den, td, tf, out + (size_t)Mrows*Dm);
    mma_gemm<1><<<dim3(Mrows/64, Dm/64, 1), 128>>>(out);
}

// round 15
// speedup vs baseline: 1.8418x; 1.0767x over previous
#include <cuda_runtime.h>
#include <cuda_bf16.h>
#include <cstdint>

#define Bsz  2
#define Tlen 512
#define Dm   256
#define Mrows (Bsz*Tlen)
#define NCH  (Bsz*Dm)        // 512 channels
#define KP   (Dm/2)          // 128 packed u32 per row

#define NC 32                // chunks per channel
#define LC (Tlen/NC)         // 16 steps per chunk

// Scratch (allocation-free rule: __device__ globals)
__device__ float    g_k  [Mrows*Dm];
__device__ float    g_v  [Mrows*Dm];
__device__ float    g_r  [Mrows*Dm];
__device__ uint32_t g_Ah [3*Mrows*KP];   // prepacked bf16-hi of mixed A (3 variants)
__device__ uint32_t g_Al [3*Mrows*KP];   // bf16-lo residual
__device__ uint32_t g_Wh [4*Dm*KP];      // Wk,Wv,Wr,Wo hi
__device__ uint32_t g_Wl [4*Dm*KP];      // lo
__device__ uint32_t g_A2h[Mrows*KP];     // wkv*sigmoid(r) hi (out-GEMM A)
__device__ uint32_t g_A2l[Mrows*KP];     // lo

// ===========================================================================
// helpers
// ===========================================================================
__device__ __forceinline__ uint32_t pack_bf16(float a, float b) {
    __nv_bfloat162 h = __floats2bfloat162_rn(a, b);
    return *reinterpret_cast<uint32_t*>(&h);
}
__device__ __forceinline__ uint32_t smem_u32(const void* p) {
    uint32_t a;
    asm("{ .reg .u64 t; cvta.to.shared.u64 t, %1; cvt.u32.u64 %0, t; }"
        : "=r"(a) : "l"(p));
    return a;
}
__device__ __forceinline__ void mma_bf16(float c[4],
                                         uint32_t a0, uint32_t a1, uint32_t a2, uint32_t a3,
                                         uint32_t b0, uint32_t b1) {
    asm volatile(
        "mma.sync.aligned.m16n8k16.row.col.f32.bf16.bf16.f32 "
        "{%0,%1,%2,%3}, {%4,%5,%6,%7}, {%8,%9}, {%0,%1,%2,%3};"
        : "+f"(c[0]), "+f"(c[1]), "+f"(c[2]), "+f"(c[3])
        : "r"(a0), "r"(a1), "r"(a2), "r"(a3), "r"(b0), "r"(b1));
}
__device__ __forceinline__ void ldmx4(uint32_t& r0, uint32_t& r1,
                                      uint32_t& r2, uint32_t& r3, uint32_t addr) {
    asm volatile("ldmatrix.sync.aligned.m8n8.x4.shared.b16 {%0,%1,%2,%3}, [%4];"
                 : "=r"(r0), "=r"(r1), "=r"(r2), "=r"(r3) : "r"(addr));
}
__device__ __forceinline__ void cp16(uint32_t dst, const void* src) {
    asm volatile("cp.async.cg.shared.global [%0], [%1], 16;" :: "r"(dst), "l"(src));
}
#define CP_COMMIT() asm volatile("cp.async.commit_group;" ::: "memory")
#define CP_WAIT(N)  asm volatile("cp.async.wait_group %0;" :: "n"(N) : "memory")

// ===========================================================================
// Prep: pack bf16 hi/lo for W (4 matrices) and mixed A (3 variants).
// ===========================================================================
#define WPREP (4*Dm*KP)          // 131072
#define APREP (3*Mrows*KP)       // 393216

__global__ void __launch_bounds__(256) prep(
    const float* __restrict__ x, const float* __restrict__ last_x,
    const float* __restrict__ mk, const float* __restrict__ mv,
    const float* __restrict__ mr,
    const float* __restrict__ Wk, const float* __restrict__ Wv,
    const float* __restrict__ Wr, const float* __restrict__ Wo)
{
    int i = blockIdx.x * 256 + threadIdx.x;
    if (i < WPREP) {
        int w   = i >> 15;               // Dm*KP = 32768 per matrix
        int rem = i & 32767;
        const float* W = (w==0) ? Wk : (w==1) ? Wv : (w==2) ? Wr : Wo;
        float2 v = *(const float2*)&W[rem*2];
        float h0 = __bfloat162float(__float2bfloat16(v.x));
        float h1 = __bfloat162float(__float2bfloat16(v.y));
        g_Wh[i] = pack_bf16(h0, h1);
        g_Wl[i] = pack_bf16(v.x - h0, v.y - h1);
    } else {
        int j   = i - WPREP;
        int z   = j >> 17;               // Mrows*KP = 131072 per variant
        int rem = j & 131071;
        int m   = rem >> 7;
        int kp  = rem & (KP-1);
        const float* mixp = (z==0) ? mk : (z==1) ? mv : mr;
        int gk = kp*2;
        int tt = m & (Tlen-1);
        float2 xc = *(const float2*)&x[(size_t)m*Dm + gk];
        float2 xp = (tt==0) ? *(const float2*)&last_x[(m>>9)*Dm + gk]
                            : *(const float2*)&x[(size_t)(m-1)*Dm + gk];
        float2 mx = *(const float2*)&mixp[gk];
        float a0 = fmaf(xc.x - xp.x, mx.x, xp.x);
        float a1 = fmaf(xc.y - xp.y, mx.y, xp.y);
        float h0 = __bfloat162float(__float2bfloat16(a0));
        float h1 = __bfloat162float(__float2bfloat16(a1));
        g_Ah[j] = pack_bf16(h0, h1);
        g_Al[j] = pack_bf16(a0 - h0, a1 - h1);
    }
}

// ===========================================================================
// GEMM: mma.sync bf16x3-split, cp.async double-buffer, ldmatrix fragments.
// Tile BMxBNx32, 128 threads, 2x2 warps, warp tile (BM/2)x(BN/2).
// Pitch 20 u32 (80B rows): 16B-aligned, conflict-free ldmatrix phases.
// ===========================================================================
#define PITCH 20

template<int MODE, int BM, int BN>
__global__ void __launch_bounds__(128) mma_gemm(float* __restrict__ out_final)
{
    constexpr int WM  = BM/2;         // warp m tile
    constexpr int WN  = BN/2;         // warp n tile
    constexpr int MI  = WM/16;        // m16 frags per warp
    constexpr int NI  = WN/8;         // n8 frags per warp
    constexpr int NH  = WN/16;        // n16 ldmatrix groups
    constexpr int CHA = BM*4;         // 16B chunks per A array per k-tile
    constexpr int CHB = BN*4;
    constexpr int CHT = 2*CHA + 2*CHB;
    constexpr int NE  = CHT/128;      // cp16 per thread per k-tile

    __shared__ uint32_t SA[2][2][BM][PITCH];   // [buf][hi/lo][row][kp]
    __shared__ uint32_t SB[2][2][BN][PITCH];

    const int tid  = threadIdx.x;
    const int wid  = tid >> 5;
    const int lane = tid & 31;
    const int g    = lane >> 2;
    const int t    = lane & 3;
    const int wm   = wid & 1;
    const int wn   = wid >> 1;
    const int m0   = blockIdx.x * BM;
    const int n0   = blockIdx.y * BN;
    const int z    = (MODE==0) ? blockIdx.z : 3;

    const uint32_t* pAh = (MODE==0) ? g_Ah + (size_t)z*Mrows*KP : g_A2h;
    const uint32_t* pAl = (MODE==0) ? g_Al + (size_t)z*Mrows*KP : g_A2l;
    const uint32_t* pWh = g_Wh + (size_t)z*Dm*KP;
    const uint32_t* pWl = g_Wl + (size_t)z*Dm*KP;
    float* outp = (MODE==0) ? ((z==0) ? g_k : (z==1) ? g_v : g_r) : out_final;

    auto stage = [&](int kt, int bb) {
        const int kp0 = kt*16;
        #pragma unroll
        for (int e = 0; e < NE; e++) {
            int c  = tid + e*128;
            int cg = (c & 3) * 4;
            const uint32_t* src;
            uint32_t dst;
            if (c < CHA) {
                int row = c >> 2;
                src = pAh + (size_t)(m0+row)*KP + kp0 + cg;
                dst = smem_u32(&SA[bb][0][row][cg]);
            } else if (c < 2*CHA) {
                int row = (c - CHA) >> 2;
                src = pAl + (size_t)(m0+row)*KP + kp0 + cg;
                dst = smem_u32(&SA[bb][1][row][cg]);
            } else if (c < 2*CHA + CHB) {
                int row = (c - 2*CHA) >> 2;
                src = pWh + (size_t)(n0+row)*KP + kp0 + cg;
                dst = smem_u32(&SB[bb][0][row][cg]);
            } else {
                int row = (c - 2*CHA - CHB) >> 2;
                src = pWl + (size_t)(n0+row)*KP + kp0 + cg;
                dst = smem_u32(&SB[bb][1][row][cg]);
            }
            cp16(dst, src);
        }
        CP_COMMIT();
    };

    float acc[MI][NI][4];
    #pragma unroll
    for (int mi=0;mi<MI;mi++)
        #pragma unroll
        for (int ni=0;ni<NI;ni++)
            #pragma unroll
            for (int q=0;q<4;q++) acc[mi][ni][q]=0.f;

    const int lrow = (lane & 7) + ((lane >> 3) & 1) * 8;
    const int lcol = (lane >> 4) * 4;

    stage(0, 0);

    const int NKT = Dm/32;   // 8
    for (int kt = 0; kt < NKT; kt++) {
        const int bb = kt & 1;
        if (kt + 1 < NKT) { stage(kt+1, bb^1); CP_WAIT(1); }
        else              { CP_WAIT(0); }
        __syncthreads();

        #pragma unroll
        for (int s = 0; s < 2; s++) {
            const int cb = s*8;
            uint32_t ah[MI][4], al[MI][4], bh[NI][2], bl[NI][2];
            #pragma unroll
            for (int mi = 0; mi < MI; mi++) {
                int r = wm*WM + mi*16 + lrow;
                ldmx4(ah[mi][0], ah[mi][1], ah[mi][2], ah[mi][3],
                      smem_u32(&SA[bb][0][r][cb + lcol]));
                ldmx4(al[mi][0], al[mi][1], al[mi][2], al[mi][3],
                      smem_u32(&SA[bb][1][r][cb + lcol]));
            }
            #pragma unroll
            for (int nh = 0; nh < NH; nh++) {
                int n = wn*WN + nh*16 + lrow;
                uint32_t q0,q1,q2,q3;
                ldmx4(q0, q1, q2, q3, smem_u32(&SB[bb][0][n][cb + lcol]));
                bh[nh*2][0]=q0; bh[nh*2+1][0]=q1; bh[nh*2][1]=q2; bh[nh*2+1][1]=q3;
                ldmx4(q0, q1, q2, q3, smem_u32(&SB[bb][1][n][cb + lcol]));
                bl[nh*2][0]=q0; bl[nh*2+1][0]=q1; bl[nh*2][1]=q2; bl[nh*2+1][1]=q3;
            }
            #pragma unroll
            for (int mi = 0; mi < MI; mi++)
                #pragma unroll
                for (int ni = 0; ni < NI; ni++) {
                    mma_bf16(acc[mi][ni], ah[mi][0],ah[mi][1],ah[mi][2],ah[mi][3],
                             bh[ni][0], bh[ni][1]);
                    mma_bf16(acc[mi][ni], ah[mi][0],ah[mi][1],ah[mi][2],ah[mi][3],
                             bl[ni][0], bl[ni][1]);
                    mma_bf16(acc[mi][ni], al[mi][0],al[mi][1],al[mi][2],al[mi][3],
                             bh[ni][0], bh[ni][1]);
                }
        }
        __syncthreads();   // all reads of buf bb done before kt+2 overwrites it
    }

    // ---- epilogue ----
    #pragma unroll
    for (int mi = 0; mi < MI; mi++) {
        #pragma unroll
        for (int ni = 0; ni < NI; ni++) {
            int m = m0 + wm*WM + mi*16 + g;
            int n = n0 + wn*WN + ni*8 + 2*t;
            *(float2*)&outp[(size_t)m*Dm + n] =
                make_float2(acc[mi][ni][0], acc[mi][ni][1]);
            *(float2*)&outp[(size_t)(m+8)*Dm + n] =
                make_float2(acc[mi][ni][2], acc[mi][ni][3]);
        }
    }
}

// ===========================================================================
// Fused WKV scan.  One block per 32 channels; threadIdx.y = chunk.
// Pass 2 writes the out-GEMM A operand (wkv*sigmoid(r)) prepacked bf16 hi/lo.
// ===========================================================================
#define PF 8
__global__ void __launch_bounds__(1024) wkv_fused(
    const float* __restrict__ x,
    const float* __restrict__ last_num,
    const float* __restrict__ last_den,
    const float* __restrict__ td,
    const float* __restrict__ tf,
    float* __restrict__ states)
{
    __shared__ float s_num[NC][33];
    __shared__ float s_den[NC][33];

    const int lane = threadIdx.x;
    const int c    = threadIdx.y;
    const int ch   = blockIdx.x * 32 + lane;
    const int b    = ch >> 8;
    const int d    = ch & (Dm-1);

    const float ew = __expf(-__expf(td[d]));
    const size_t base = (size_t)b*Tlen*Dm + (size_t)c*LC*Dm + d;
    const float* kp = g_k + base;
    const float* vp = g_v + base;
    const float* rp = g_r + base;

    float ka[PF], va[PF], kb[PF], vb[PF];
    #pragma unroll
    for (int i=0;i<PF;i++){ ka[i]=kp[i*Dm];        va[i]=vp[i*Dm]; }
    #pragma unroll
    for (int i=0;i<PF;i++){ kb[i]=kp[(PF+i)*Dm];   vb[i]=vp[(PF+i)*Dm]; }

    float num = 0.f, den = 0.f;
    float ea[PF], eb[PF];
    #pragma unroll
    for (int i=0;i<PF;i++) ea[i] = __expf(ka[i]);
    #pragma unroll
    for (int i=0;i<PF;i++) eb[i] = __expf(kb[i]);
    #pragma unroll
    for (int i=0;i<PF;i++){ num = fmaf(ew, num, ea[i]*va[i]); den = fmaf(ew, den, ea[i]); }
    #pragma unroll
    for (int i=0;i<PF;i++){ num = fmaf(ew, num, eb[i]*vb[i]); den = fmaf(ew, den, eb[i]); }

    s_num[c][lane] = num;
    s_den[c][lane] = den;
    __syncthreads();

    if (c == 0) {
        float e2 = ew*ew, e4 = e2*e2, e8 = e4*e4;
        float ewL = e8*e8;                 // ew^16
        float rn = last_num[ch];
        float rd = last_den[ch];
        #pragma unroll
        for (int cc = 0; cc < NC; cc++) {
            float tn  = s_num[cc][lane];
            float tdn = s_den[cc][lane];
            s_num[cc][lane] = rn;
            s_den[cc][lane] = rd;
            rn = fmaf(ewL, rn, tn);
            rd = fmaf(ewL, rd, tdn);
        }
        states[ch]         = x[((size_t)b*Tlen + Tlen-1)*Dm + d];
        states[NCH + ch]   = rn;
        states[2*NCH + ch] = rd;
    }
    __syncthreads();

    num = s_num[c][lane];
    den = s_den[c][lane];
    const float eu = __expf(tf[d]);
    const int mrow0 = b*Tlen + c*LC;
    const int kpcol = d >> 1;
    const bool even = (lane & 1) == 0;

    float ra[PF], rb[PF];
    #pragma unroll
    for (int i=0;i<PF;i++) ra[i] = rp[i*Dm];
    #pragma unroll
    for (int i=0;i<PF;i++) rb[i] = rp[(PF+i)*Dm];

    #pragma unroll
    for (int i=0;i<PF;i++){
        float ekv = ea[i]*va[i];
        float wkv = __fdividef(fmaf(eu, ekv, num), fmaf(eu, ea[i], den));
        float a   = wkv * __fdividef(1.f, 1.f + __expf(-ra[i]));
        float an  = __shfl_down_sync(0xffffffffu, a, 1);
        if (even) {
            float h0 = __bfloat162float(__float2bfloat16(a));
            float h1 = __bfloat162float(__float2bfloat16(an));
            size_t o = (size_t)(mrow0 + i)*KP + kpcol;
            g_A2h[o] = pack_bf16(h0, h1);
            g_A2l[o] = pack_bf16(a - h0, an - h1);
        }
        num = fmaf(ew, num, ekv);
        den = fmaf(ew, den, ea[i]);
    }
    #pragma unroll
    for (int i=0;i<PF;i++){
        float ekv = eb[i]*vb[i];
        float wkv = __fdividef(fmaf(eu, ekv, num), fmaf(eu, eb[i], den));
        float a   = wkv * __fdividef(1.f, 1.f + __expf(-rb[i]));
        float an  = __shfl_down_sync(0xffffffffu, a, 1);
        if (even) {
            float h0 = __bfloat162float(__float2bfloat16(a));
            float h1 = __bfloat162float(__float2bfloat16(an));
            size_t o = (size_t)(mrow0 + PF + i)*KP + kpcol;
            g_A2h[o] = pack_bf16(h0, h1);
            g_A2l[o] = pack_bf16(a - h0, an - h1);
        }
        num = fmaf(ew, num, ekv);
        den = fmaf(ew, den, eb[i]);
    }
}

// ---------------------------------------------------------------------------
extern "C" void kernel_launch(void* const* d_in, const int* in_sizes, int n_in,
                              void* d_out, int out_size)
{
    const float* x        = (const float*)d_in[0];
    const float* last_x   = (const float*)d_in[1];
    const float* last_num = (const float*)d_in[2];
    const float* last_den = (const float*)d_in[3];
    const float* td       = (const float*)d_in[4];
    const float* tf       = (const float*)d_in[5];
    const float* mk       = (const float*)d_in[6];
    const float* mv       = (const float*)d_in[7];
    const float* mr       = (const float*)d_in[8];
    const float* Wk       = (const float*)d_in[9];
    const float* Wv       = (const float*)d_in[10];
    const float* Wr       = (const float*)d_in[11];
    const float* Wo       = (const float*)d_in[12];
    float* out = (float*)d_out;

    prep<<<(WPREP+APREP)/256, 256>>>(x, last_x, mk, mv, mr, Wk, Wv, Wr, Wo);
    mma_gemm<0,32,64><<<dim3(Mrows/32, Dm/64, 3), 128>>>(nullptr);
    wkv_fused<<<NCH/32, dim3(32,32)>>>(
        x, last_num, last_den, td, tf, out + (size_t)Mrows*Dm);
    mma_gemm<1,32,32><<<dim3(Mrows/32, Dm/32, 1), 128>>>(out);
}